// round 10
// baseline (speedup 1.0000x reference)
#include <cuda_runtime.h>

// FFT long conv, N = 16384 = 4^7, one CTA per row. R10:
// SoA packed-f32x2 version: each thread processes its 2 butterflies per pass as
// one f32x2-packed pair (add/mul/fma.rn.f32x2 -> FADD2/FFMA2, 2 FLOP/issue).
// SMEM = two scalar float planes (re, im), each skewed i+(i>>4).
// Pass structure unchanged from R9: fused gmem load pass (S=1024, zero upper half),
// radix-16 S=64, S=4, fused middle (combine), then inverse mirror with fused store.

#define L_SIG  8192
#define N_FFT  16384
#define NT     512
#define PLANE  (N_FFT + (N_FFT >> 4))      // 17408 floats per plane
#define SMEM_BYTES (2 * PLANE * 4)         // 139264 B

typedef unsigned long long u64;

__device__ __forceinline__ int SKEWF(int i) { return i + (i >> 4); }

// ---- packed f32x2 primitives ----
__device__ __forceinline__ u64 pk(float lo, float hi) {
    u64 r;
    asm("mov.b64 %0, {%1, %2};" : "=l"(r) : "r"(__float_as_uint(lo)), "r"(__float_as_uint(hi)));
    return r;
}
__device__ __forceinline__ void upk(u64 v, float& lo, float& hi) {
    unsigned a, b;
    asm("mov.b64 {%0, %1}, %2;" : "=r"(a), "=r"(b) : "l"(v));
    lo = __uint_as_float(a); hi = __uint_as_float(b);
}
__device__ __forceinline__ u64 psplat(float v) { return pk(v, v); }
__device__ __forceinline__ u64 padd(u64 a, u64 b) {
    u64 r; asm("add.rn.f32x2 %0, %1, %2;" : "=l"(r) : "l"(a), "l"(b)); return r;
}
__device__ __forceinline__ u64 pmul(u64 a, u64 b) {
    u64 r; asm("mul.rn.f32x2 %0, %1, %2;" : "=l"(r) : "l"(a), "l"(b)); return r;
}
__device__ __forceinline__ u64 pfma(u64 a, u64 b, u64 c) {
    u64 r; asm("fma.rn.f32x2 %0, %1, %2, %3;" : "=l"(r) : "l"(a), "l"(b), "l"(c)); return r;
}
__device__ __forceinline__ u64 pneg(u64 a) {            // flip both sign bits (ALU pipe)
    u64 r; asm("xor.b64 %0, %1, 0x8000000080000000;" : "=l"(r) : "l"(a)); return r;
}
__device__ __forceinline__ u64 psub(u64 a, u64 b) {     // a - b = fma(b, -1, a): 1 issue
    const u64 NEG1 = 0xBF800000BF800000ULL;
    u64 r; asm("fma.rn.f32x2 %0, %1, %2, %3;" : "=l"(r) : "l"(b), "l"(NEG1), "l"(a)); return r;
}

// packed complex pair (SoA over 2 butterflies)
struct pc { u64 re, im; };
struct tw3 { u64 re, im, nim; };

__device__ __forceinline__ tw3 mktw(pc w) { tw3 t; t.re = w.re; t.im = w.im; t.nim = pneg(w.im); return t; }
// a * w  (w with precomputed negated imag): 4 fma-pipe issues for 2 butterflies
__device__ __forceinline__ pc ctw(pc a, tw3 w) {
    pc r;
    r.re = pfma(a.im, w.nim, pmul(a.re, w.re));
    r.im = pfma(a.im, w.re,  pmul(a.re, w.im));
    return r;
}
// full complex multiply (for twiddle power chain)
__device__ __forceinline__ pc cmulpc(pc a, pc b) {
    pc r;
    r.re = pfma(a.im, pneg(b.im), pmul(a.re, b.re));
    r.im = pfma(a.im, b.re,       pmul(a.re, b.im));
    return r;
}
// a * (c + i*s) with compile-time scalar constants
__device__ __forceinline__ pc cmulc(pc a, float c, float s) {
    pc r;
    r.re = pfma(a.im, psplat(-s), pmul(a.re, psplat(c)));
    r.im = pfma(a.im, psplat(c),  pmul(a.re, psplat(s)));
    return r;
}

__device__ __forceinline__ void pdft4_fwd(pc& a0, pc& a1, pc& a2, pc& a3) {
    pc t0, t1, t2, t3;
    t0.re = padd(a0.re, a2.re); t0.im = padd(a0.im, a2.im);
    t1.re = psub(a0.re, a2.re); t1.im = psub(a0.im, a2.im);
    t2.re = padd(a1.re, a3.re); t2.im = padd(a1.im, a3.im);
    t3.re = psub(a1.re, a3.re); t3.im = psub(a1.im, a3.im);
    a0.re = padd(t0.re, t2.re); a0.im = padd(t0.im, t2.im);
    a2.re = psub(t0.re, t2.re); a2.im = psub(t0.im, t2.im);
    a1.re = padd(t1.re, t3.im); a1.im = psub(t1.im, t3.re);   // t1 - i*t3
    a3.re = psub(t1.re, t3.im); a3.im = padd(t1.im, t3.re);   // t1 + i*t3
}
__device__ __forceinline__ void pdft4_inv(pc& a0, pc& a1, pc& a2, pc& a3) {
    pc t0, t1, t2, t3;
    t0.re = padd(a0.re, a2.re); t0.im = padd(a0.im, a2.im);
    t1.re = psub(a0.re, a2.re); t1.im = psub(a0.im, a2.im);
    t2.re = padd(a1.re, a3.re); t2.im = padd(a1.im, a3.im);
    t3.re = psub(a1.re, a3.re); t3.im = psub(a1.im, a3.im);
    a0.re = padd(t0.re, t2.re); a0.im = padd(t0.im, t2.im);
    a2.re = psub(t0.re, t2.re); a2.im = psub(t0.im, t2.im);
    a1.re = psub(t1.re, t3.im); a1.im = padd(t1.im, t3.re);   // t1 + i*t3
    a3.re = padd(t1.re, t3.im); a3.im = psub(t1.im, t3.re);   // t1 - i*t3
}

// cos/sin(2*pi*k/16) tables, k in 0..9
__device__ __forceinline__ float OC16(int k) {
    const float t[10] = {1.f, 0.9238795325f, 0.7071067812f, 0.3826834324f, 0.f,
                         -0.3826834324f, -0.7071067812f, -0.9238795325f, -1.f, -0.9238795325f};
    return t[k];
}
__device__ __forceinline__ float OS16(int k) {     // sin(2*pi*k/16), positive convention
    const float t[10] = {0.f, 0.3826834324f, 0.7071067812f, 0.9238795325f, 1.f,
                         0.9238795325f, 0.7071067812f, 0.3826834324f, 0.f, -0.3826834324f};
    return t[k];
}

// reverse six base-4 digits of a 12-bit value
__device__ __forceinline__ int rev6_base4(int c) {
    unsigned r = __brev((unsigned)c) >> 20;
    return (int)(((r & 0xAAAu) >> 1) | ((r & 0x555u) << 1));
}

// ---- fused forward pass S=1024: gmem -> planes, upper half implicit zero ----
__device__ __forceinline__ void pass1(float* zre, float* zim,
                                      const float* __restrict__ xr,
                                      const float* __restrict__ hr, int tid) {
    const int j0 = tid, j1 = tid + NT;
    pc in[8];
    #pragma unroll
    for (int r = 0; r < 8; r++) {
        in[r].re = pk(xr[j0 + 1024 * r], xr[j1 + 1024 * r]);
        in[r].im = pk(hr[j0 + 1024 * r], hr[j1 + 1024 * r]);
    }
    const float tstep = -6.2831853071795864f / 16384.0f;
    float sn0, cs0, sn1, cs1;
    __sincosf(tstep * (float)j0, &sn0, &cs0);
    __sincosf(tstep * (float)j1, &sn1, &cs1);
    pc W;  W.re = pk(cs0, cs1); W.im = pk(sn0, sn1);
    pc W2 = cmulpc(W, W), W3 = cmulpc(W2, W);
    tw3 tW = mktw(W), tW2 = mktw(W2), tW3 = mktw(W3);

    pc b[16];
    #pragma unroll
    for (int r0 = 0; r0 < 4; r0++) {             // level m = 4096, a2=a3=0
        pc a0 = in[r0], a1 = in[r0 + 4];
        pc y0, y1, y2, y3;
        y0.re = padd(a0.re, a1.re); y0.im = padd(a0.im, a1.im);
        y2.re = psub(a0.re, a1.re); y2.im = psub(a0.im, a1.im);
        y1.re = padd(a0.re, a1.im); y1.im = psub(a0.im, a1.re);   // a0 - i*a1
        y3.re = psub(a0.re, a1.im); y3.im = padd(a0.im, a1.re);   // a0 + i*a1
        b[r0] = y0;
        if (r0 == 0) {
            b[4]  = ctw(y1, tW);
            b[8]  = ctw(y2, tW2);
            b[12] = ctw(y3, tW3);
        } else {
            b[r0 + 4]  = ctw(y1, mktw(cmulc(W,  OC16(r0),     -OS16(r0))));
            b[r0 + 8]  = ctw(y2, mktw(cmulc(W2, OC16(2 * r0), -OS16(2 * r0))));
            b[r0 + 12] = ctw(y3, mktw(cmulc(W3, OC16(3 * r0), -OS16(3 * r0))));
        }
    }
    pc W4 = cmulpc(W2, W2), W8 = cmulpc(W4, W4), W12 = cmulpc(W8, W4);
    tw3 tW4 = mktw(W4), tW8 = mktw(W8), tW12 = mktw(W12);
    #pragma unroll
    for (int d = 0; d < 4; d++) {                // level m = 1024
        pc a0 = b[4*d], a1 = b[4*d+1], a2 = b[4*d+2], a3 = b[4*d+3];
        pdft4_fwd(a0, a1, a2, a3);
        b[4*d]   = a0;
        b[4*d+1] = ctw(a1, tW4);
        b[4*d+2] = ctw(a2, tW8);
        b[4*d+3] = ctw(a3, tW12);
    }
    #pragma unroll
    for (int r = 0; r < 16; r++) {
        int i0 = SKEWF(j0 + 1024 * r), i1 = SKEWF(j1 + 1024 * r);
        float f0, f1, g0, g1;
        upk(b[r].re, f0, f1); upk(b[r].im, g0, g1);
        zre[i0] = f0; zre[i1] = f1; zim[i0] = g0; zim[i1] = g1;
    }
}

// ---- generic middle radix-16 pass (S = 64 or 4); both halves share j -> one sincos ----
template<int S, bool INV>
__device__ __forceinline__ void pass_mid(float* zre, float* zim, int tid) {
    const int j = tid & (S - 1);
    const int base0 = (tid / S) * (16 * S) + j;   // second half at base0 + 8192
    pc b[16];
    #pragma unroll
    for (int r = 0; r < 16; r++) {
        int i0 = SKEWF(base0 + S * r), i1 = SKEWF(base0 + 8192 + S * r);
        b[r].re = pk(zre[i0], zre[i1]);
        b[r].im = pk(zim[i0], zim[i1]);
    }
    const float ang = (INV ? 6.2831853071795864f : -6.2831853071795864f) / (16.0f * (float)S);
    float sn, cs;
    __sincosf(ang * (float)j, &sn, &cs);
    pc W;  W.re = psplat(cs); W.im = psplat(sn);
    pc W2 = cmulpc(W, W);

    if (!INV) {
        pc W3 = cmulpc(W2, W);
        tw3 tW = mktw(W), tW2 = mktw(W2), tW3 = mktw(W3);
        #pragma unroll
        for (int r0 = 0; r0 < 4; r0++) {         // level m = 4S
            pc a0 = b[r0], a1 = b[r0+4], a2 = b[r0+8], a3 = b[r0+12];
            pdft4_fwd(a0, a1, a2, a3);
            b[r0] = a0;
            if (r0 == 0) {
                b[4]  = ctw(a1, tW);
                b[8]  = ctw(a2, tW2);
                b[12] = ctw(a3, tW3);
            } else {
                b[r0 + 4]  = ctw(a1, mktw(cmulc(W,  OC16(r0),     -OS16(r0))));
                b[r0 + 8]  = ctw(a2, mktw(cmulc(W2, OC16(2 * r0), -OS16(2 * r0))));
                b[r0 + 12] = ctw(a3, mktw(cmulc(W3, OC16(3 * r0), -OS16(3 * r0))));
            }
        }
        pc W4 = cmulpc(W2, W2), W8 = cmulpc(W4, W4), W12 = cmulpc(W8, W4);
        tw3 tW4 = mktw(W4), tW8 = mktw(W8), tW12 = mktw(W12);
        #pragma unroll
        for (int d = 0; d < 4; d++) {            // level m = S
            pc a0 = b[4*d], a1 = b[4*d+1], a2 = b[4*d+2], a3 = b[4*d+3];
            pdft4_fwd(a0, a1, a2, a3);
            b[4*d]   = a0;
            b[4*d+1] = ctw(a1, tW4);
            b[4*d+2] = ctw(a2, tW8);
            b[4*d+3] = ctw(a3, tW12);
        }
    } else {
        pc W4 = cmulpc(W2, W2), W8 = cmulpc(W4, W4), W12 = cmulpc(W8, W4);
        tw3 tW4 = mktw(W4), tW8 = mktw(W8), tW12 = mktw(W12);
        #pragma unroll
        for (int d = 0; d < 4; d++) {            // level m = S
            pc a0 = b[4*d];
            pc a1 = ctw(b[4*d+1], tW4);
            pc a2 = ctw(b[4*d+2], tW8);
            pc a3 = ctw(b[4*d+3], tW12);
            pdft4_inv(a0, a1, a2, a3);
            b[4*d] = a0; b[4*d+1] = a1; b[4*d+2] = a2; b[4*d+3] = a3;
        }
        pc W3 = cmulpc(W2, W);
        tw3 tW = mktw(W), tW2 = mktw(W2), tW3 = mktw(W3);
        #pragma unroll
        for (int r0 = 0; r0 < 4; r0++) {         // level m = 4S
            pc a0 = b[r0];
            pc a1, a2, a3;
            if (r0 == 0) {
                a1 = ctw(b[4],  tW);
                a2 = ctw(b[8],  tW2);
                a3 = ctw(b[12], tW3);
            } else {
                a1 = ctw(b[r0 + 4],  mktw(cmulc(W,  OC16(r0),     OS16(r0))));
                a2 = ctw(b[r0 + 8],  mktw(cmulc(W2, OC16(2 * r0), OS16(2 * r0))));
                a3 = ctw(b[r0 + 12], mktw(cmulc(W3, OC16(3 * r0), OS16(3 * r0))));
            }
            pdft4_inv(a0, a1, a2, a3);
            b[r0] = a0; b[r0 + 4] = a1; b[r0 + 8] = a2; b[r0 + 12] = a3;
        }
    }
    #pragma unroll
    for (int r = 0; r < 16; r++) {
        int i0 = SKEWF(base0 + S * r), i1 = SKEWF(base0 + 8192 + S * r);
        float f0, f1, g0, g1;
        upk(b[r].re, f0, f1); upk(b[r].im, g0, g1);
        zre[i0] = f0; zre[i1] = f1; zim[i0] = g0; zim[i1] = g1;
    }
}

// ---- fused inverse pass S=1024: planes -> gmem, Re(outputs 0..8191)*scale only ----
__device__ __forceinline__ void pass7(const float* zre, const float* zim,
                                      float* __restrict__ yr, int tid) {
    const int j0 = tid, j1 = tid + NT;
    pc b[16];
    #pragma unroll
    for (int r = 0; r < 16; r++) {
        int i0 = SKEWF(j0 + 1024 * r), i1 = SKEWF(j1 + 1024 * r);
        b[r].re = pk(zre[i0], zre[i1]);
        b[r].im = pk(zim[i0], zim[i1]);
    }
    const float tstep = 6.2831853071795864f / 16384.0f;
    float sn0, cs0, sn1, cs1;
    __sincosf(tstep * (float)j0, &sn0, &cs0);
    __sincosf(tstep * (float)j1, &sn1, &cs1);
    pc W;  W.re = pk(cs0, cs1); W.im = pk(sn0, sn1);
    pc W2 = cmulpc(W, W);
    pc W4 = cmulpc(W2, W2), W8 = cmulpc(W4, W4), W12 = cmulpc(W8, W4);
    tw3 tW4 = mktw(W4), tW8 = mktw(W8), tW12 = mktw(W12);
    #pragma unroll
    for (int d = 0; d < 4; d++) {                // level m = 1024 (full complex)
        pc a0 = b[4*d];
        pc a1 = ctw(b[4*d+1], tW4);
        pc a2 = ctw(b[4*d+2], tW8);
        pc a3 = ctw(b[4*d+3], tW12);
        pdft4_inv(a0, a1, a2, a3);
        b[4*d] = a0; b[4*d+1] = a1; b[4*d+2] = a2; b[4*d+3] = a3;
    }
    pc W3 = cmulpc(W2, W);
    const u64 sc = psplat(1.0f / (16384.0f * 16384.0f));
    #pragma unroll
    for (int r0 = 0; r0 < 4; r0++) {             // level m = 4096: Re of outputs 0..8191
        pc w1 = (r0 == 0) ? W  : cmulc(W,  OC16(r0),     OS16(r0));
        pc w2 = (r0 == 0) ? W2 : cmulc(W2, OC16(2 * r0), OS16(2 * r0));
        pc w3 = (r0 == 0) ? W3 : cmulc(W3, OC16(3 * r0), OS16(3 * r0));
        pc in0 = b[r0];
        pc in1 = ctw(b[r0 + 4],  mktw(w1));
        u64 in2x = pfma(b[r0 + 8].im, pneg(w2.im), pmul(b[r0 + 8].re, w2.re));  // Re only
        pc in3 = ctw(b[r0 + 12], mktw(w3));
        u64 re0 = padd(padd(in0.re, in2x), padd(in1.re, in3.re));
        u64 re1 = psub(psub(in0.re, in2x), psub(in1.im, in3.im));
        re0 = pmul(re0, sc); re1 = pmul(re1, sc);
        float o00, o01, o10, o11;
        upk(re0, o00, o01); upk(re1, o10, o11);
        yr[j0 + 1024 * r0]       = o00;
        yr[j1 + 1024 * r0]       = o01;
        yr[j0 + 1024 * (r0 + 4)] = o10;
        yr[j1 + 1024 * (r0 + 4)] = o11;
    }
}

// ---- fused middle: fwd radix-4 (m=1) + spectral combine + inv radix-4 (m=1); scalar ----
__device__ __forceinline__ float2 cadds(float2 a, float2 b) { return make_float2(a.x+b.x, a.y+b.y); }
__device__ __forceinline__ float2 csubs(float2 a, float2 b) { return make_float2(a.x-b.x, a.y-b.y); }
__device__ __forceinline__ float2 cmuls(float2 a, float2 b) {
    return make_float2(fmaf(a.x, b.x, -a.y * b.y), fmaf(a.x, b.y, a.y * b.x));
}
__device__ __forceinline__ void sdft4_fwd(float2& a0, float2& a1, float2& a2, float2& a3) {
    float2 t0 = cadds(a0,a2), t1 = csubs(a0,a2), t2 = cadds(a1,a3), t3 = csubs(a1,a3);
    a0 = cadds(t0,t2); a2 = csubs(t0,t2);
    a1 = make_float2(t1.x + t3.y, t1.y - t3.x);
    a3 = make_float2(t1.x - t3.y, t1.y + t3.x);
}
__device__ __forceinline__ void sdft4_inv(float2& a0, float2& a1, float2& a2, float2& a3) {
    float2 t0 = cadds(a0,a2), t1 = csubs(a0,a2), t2 = cadds(a1,a3), t3 = csubs(a1,a3);
    a0 = cadds(t0,t2); a2 = csubs(t0,t2);
    a1 = make_float2(t1.x - t3.y, t1.y + t3.x);
    a3 = make_float2(t1.x + t3.y, t1.y - t3.x);
}

__device__ __forceinline__ void fused_mid(float* zre, float* zim, int tid) {
    for (int c = tid; c < N_FFT / 4; c += NT) {
        if (c == 0) {
            float2 A0 = make_float2(zre[SKEWF(0)], zim[SKEWF(0)]);
            float2 A1 = make_float2(zre[SKEWF(1)], zim[SKEWF(1)]);
            float2 A2 = make_float2(zre[SKEWF(2)], zim[SKEWF(2)]);
            float2 A3 = make_float2(zre[SKEWF(3)], zim[SKEWF(3)]);
            sdft4_fwd(A0, A1, A2, A3);           // freqs 0, 4096, 8192, 12288
            float2 Y0 = make_float2(A0.x * A0.y, 0.0f);
            float2 Y2 = make_float2(A2.x * A2.y, 0.0f);
            float2 Za = A1, Zb = A3;
            float2 X = make_float2(0.5f * (Za.x + Zb.x), 0.5f * (Za.y - Zb.y));
            float2 H = make_float2(0.5f * (Za.y + Zb.y), 0.5f * (Zb.x - Za.x));
            float2 Y1 = cmuls(X, H);
            float2 Y3 = make_float2(Y1.x, -Y1.y);
            sdft4_inv(Y0, Y1, Y2, Y3);
            zre[SKEWF(0)] = Y0.x; zim[SKEWF(0)] = Y0.y;
            zre[SKEWF(1)] = Y1.x; zim[SKEWF(1)] = Y1.y;
            zre[SKEWF(2)] = Y2.x; zim[SKEWF(2)] = Y2.y;
            zre[SKEWF(3)] = Y3.x; zim[SKEWF(3)] = Y3.y;
            continue;
        }
        const int k0 = rev6_base4(c);
        const int cp = rev6_base4(4096 - k0);
        if (c > cp) continue;

        float2 A[4], B[4];
        #pragma unroll
        for (int t = 0; t < 4; t++) {
            int ia = SKEWF(4 * c + t), ib = SKEWF(4 * cp + t);
            A[t] = make_float2(zre[ia], zim[ia]);
            B[t] = make_float2(zre[ib], zim[ib]);
        }
        sdft4_fwd(A[0], A[1], A[2], A[3]);
        sdft4_fwd(B[0], B[1], B[2], B[3]);
        float2 An[4], Bn[4];
        #pragma unroll
        for (int t = 0; t < 4; t++) {
            float2 Za = A[t], Zb = B[3 - t];
            float2 X = make_float2(0.5f * (Za.x + Zb.x), 0.5f * (Za.y - Zb.y));
            float2 H = make_float2(0.5f * (Za.y + Zb.y), 0.5f * (Zb.x - Za.x));
            float2 Y = cmuls(X, H);
            An[t] = Y;
            Bn[3 - t] = make_float2(Y.x, -Y.y);
        }
        sdft4_inv(An[0], An[1], An[2], An[3]);
        sdft4_inv(Bn[0], Bn[1], Bn[2], Bn[3]);
        #pragma unroll
        for (int t = 0; t < 4; t++) {
            int ia = SKEWF(4 * c + t), ib = SKEWF(4 * cp + t);
            zre[ia] = An[t].x; zim[ia] = An[t].y;
            zre[ib] = Bn[t].x; zim[ib] = Bn[t].y;
        }
    }
}

__global__ __launch_bounds__(NT, 1)
void fftconv_kernel(const float* __restrict__ x, const float* __restrict__ h,
                    float* __restrict__ y) {
    extern __shared__ float smem[];
    float* zre = smem;
    float* zim = smem + PLANE;
    const int row = blockIdx.x;
    const int tid = threadIdx.x;
    const float* xr = x + (size_t)row * L_SIG;
    const float* hr = h + (size_t)row * L_SIG;
    float* yr = y + (size_t)row * L_SIG;

    pass1(zre, zim, xr, hr, tid);        __syncthreads();
    pass_mid<64, false>(zre, zim, tid);  __syncthreads();
    pass_mid<4,  false>(zre, zim, tid);  __syncthreads();
    fused_mid(zre, zim, tid);            __syncthreads();
    pass_mid<4,  true >(zre, zim, tid);  __syncthreads();
    pass_mid<64, true >(zre, zim, tid);  __syncthreads();
    pass7(zre, zim, yr, tid);
}

extern "C" void kernel_launch(void* const* d_in, const int* in_sizes, int n_in,
                              void* d_out, int out_size) {
    const float* x = (const float*)d_in[0];
    const float* h = (const float*)d_in[1];
    float* y = (float*)d_out;

    cudaFuncSetAttribute(fftconv_kernel,
                         cudaFuncAttributeMaxDynamicSharedMemorySize, SMEM_BYTES);

    const int B = in_sizes[0] / L_SIG;   // 4096 rows
    fftconv_kernel<<<B, NT, SMEM_BYTES>>>(x, h, y);
}